// round 8
// baseline (speedup 1.0000x reference)
#include <cuda_runtime.h>
#include <math.h>

// Problem constants (fixed by Dense_test reference)
#define B_TOT   512
#define T_STEPS 2000
#define N_INP   32
#define N_HID   200
#define N_OUT   3
#define KDIM    (N_INP + N_HID)   // 232
#define NB      4                 // batches per CTA
#define NCTA    (B_TOT / NB)      // 128
#define NTHR    256

// dynamic smem: Wt[KDIM][N_HID] floats + ksh float4[KDIM]
#define SMEM_WT_FLOATS (KDIM * N_HID)          // 46400 floats = 185600 B (16B aligned)
#define SMEM_BYTES     (SMEM_WT_FLOATS * 4 + KDIM * 16)

__device__ __forceinline__ float sigm(float v) {
    return 1.0f / (1.0f + expf(-v));
}

__device__ __forceinline__ unsigned long long pack_dup(float w) {
    unsigned long long r;
    asm("mov.b64 %0, {%1, %1};" : "=l"(r) : "f"(w));
    return r;
}

__device__ __forceinline__ void fma_x2(unsigned long long& acc,
                                       unsigned long long a,
                                       unsigned long long b) {
    asm("fma.rn.f32x2 %0, %1, %2, %3;" : "=l"(acc) : "l"(a), "l"(b), "l"(acc));
}

__device__ __forceinline__ void unpack2(unsigned long long v, float& lo, float& hi) {
    asm("mov.b64 {%0, %1}, %2;" : "=f"(lo), "=f"(hi) : "l"(v));
}

extern __shared__ float smem[];

__global__ void __launch_bounds__(NTHR, 1)
snn_dense_kernel(const float* __restrict__ x,
                 const float* __restrict__ W1,
                 const float* __restrict__ b1,
                 const float* __restrict__ tau_n,
                 const float* __restrict__ tau_m1,
                 const float* __restrict__ W2,
                 const float* __restrict__ b2,
                 const float* __restrict__ tau_m2,
                 const float* __restrict__ mask,
                 float* __restrict__ out)
{
    float*  Wt   = smem;                                    // [KDIM][N_HID], transposed masked W1
    float4* ksh4 = (float4*)(smem + SMEM_WT_FLOATS);        // [KDIM] : one float per local batch
    float*  kshf = (float*)ksh4;

    const int tid = threadIdx.x;
    const int b0  = blockIdx.x * NB;

    // Stage masked, transposed weights into shared (coalesced global reads).
    for (int idx = tid; idx < N_HID * KDIM; idx += NTHR) {
        int n = idx / KDIM;
        int i = idx - n * KDIM;
        Wt[i * N_HID + n] = W1[idx] * mask[idx];
    }
    // Zero the k buffer (spike region must start at 0; x region overwritten each step).
    for (int idx = tid; idx < KDIM * NB; idx += NTHR) kshf[idx] = 0.0f;

    const int  n      = tid;
    const bool active = (n < N_HID);

    float beta = 0.f, omb = 0.f, a1 = 0.f, oma1 = 0.f, b1n = 0.f;
    if (active) {
        beta = sigm(tau_n[n]);   omb  = 1.0f - beta;
        a1   = sigm(tau_m1[n]);  oma1 = 1.0f - a1;
        b1n  = b1[n];
    }
    float a2[N_OUT];
#pragma unroll
    for (int o = 0; o < N_OUT; ++o) a2[o] = sigm(tau_m2[o]);

    // x prefetch: threads 0..127 each own one (local batch, input idx).
    const float* xptr = nullptr;
    float        xreg = 0.f;
    const int    xb   = tid >> 5;     // local batch 0..3
    const int    xi   = tid & 31;     // input index 0..31
    if (tid < NB * N_INP) {
        xptr = x + ((size_t)(b0 + xb) * T_STEPS) * N_INP + xi;
        xreg = __ldg(xptr);           // t = 0
    }

    // Per-thread state for neuron n across 4 batches.
    float mem1[NB] = {0.f, 0.f, 0.f, 0.f};
    float dcur[NB] = {0.f, 0.f, 0.f, 0.f};
    float spk [NB] = {0.f, 0.f, 0.f, 0.f};
    float Us  [NB] = {0.f, 0.f, 0.f, 0.f};   // sum of spikes, t>=1
    float spk0[NB] = {0.f, 0.f, 0.f, 0.f};   // spike at t==0
    float Wac[N_OUT][NB];                     // leaky spike filter per output decay
#pragma unroll
    for (int o = 0; o < N_OUT; ++o)
#pragma unroll
        for (int b = 0; b < NB; ++b) Wac[o][b] = 0.f;

    __syncthreads();   // weights staged, spike region zeroed

    for (int t = 0; t < T_STEPS; ++t) {
        // publish x_t into k buffer
        if (tid < NB * N_INP) kshf[xi * NB + xb] = xreg;
        __syncthreads();   // x_t + spikes(t-1) visible to everyone

        // prefetch x_{t+1} (latency hidden under the dot products)
        if (tid < NB * N_INP && (t + 1) < T_STEPS)
            xreg = __ldg(xptr + (size_t)(t + 1) * N_INP);

        if (active) {
            // cur[b] = dot(Wm[n,:], k[b,:]) + b1[n], 4 batches via packed f32x2 FMA
            unsigned long long acc01 = pack_dup(b1n);
            unsigned long long acc23 = acc01;
            const float*      wcol = Wt + n;
            const ulonglong2* kk   = (const ulonglong2*)ksh4;
#pragma unroll 8
            for (int i = 0; i < KDIM; ++i) {
                unsigned long long wpk = pack_dup(wcol[i * N_HID]);
                ulonglong2         kv  = kk[i];
                fma_x2(acc01, wpk, kv.x);
                fma_x2(acc23, wpk, kv.y);
            }
            float cur[NB];
            unpack2(acc01, cur[0], cur[1]);
            unpack2(acc23, cur[2], cur[3]);

#pragma unroll
            for (int b = 0; b < NB; ++b) {
                dcur[b] = fmaf(beta, dcur[b], omb * cur[b]);          // dendritic filter
                mem1[b] = fmaf(a1, mem1[b], oma1 * dcur[b]) - spk[b]; // soft reset (old spike)
                spk[b]  = (mem1[b] > 1.0f) ? 1.0f : 0.0f;             // VTH = 1
            }
#pragma unroll
            for (int o = 0; o < N_OUT; ++o)
#pragma unroll
                for (int b = 0; b < NB; ++b)
                    Wac[o][b] = fmaf(a2[o], Wac[o][b], spk[b]);       // W(t)=a2*W+spk

            if (t == 0) {
#pragma unroll
                for (int b = 0; b < NB; ++b) spk0[b] = spk[b];
            } else {
#pragma unroll
                for (int b = 0; b < NB; ++b) Us[b] += spk[b];
            }
        }
        __syncthreads();   // all reads of k buffer complete

        if (active) {      // publish spikes(t) for next step
            ksh4[N_INP + n] = make_float4(spk[0], spk[1], spk[2], spk[3]);
        }
    }

    // ---- epilogue: result[b][o] = (sum_n W2[o,n]*A_o[n,b] + b2[o]*S_c[o]) / T ----
    __syncthreads();
    float* red = smem;   // reuse weight region: [12][N_HID]
    if (active) {
#pragma unroll
        for (int o = 0; o < N_OUT; ++o)
#pragma unroll
            for (int b = 0; b < NB; ++b)
                red[(o * NB + b) * N_HID + n] = Us[b] + a2[o] * (spk0[b] - Wac[o][b]);
    }
    __syncthreads();

    if (tid < N_OUT * NB) {
        const int o = tid / NB;
        const int b = tid % NB;
        const float* Arow = red + tid * N_HID;
        const float* w2r  = W2 + o * N_HID;
        float s = 0.f;
#pragma unroll 8
        for (int j = 0; j < N_HID; ++j) s = fmaf(__ldg(w2r + j), Arow[j], s);

        // S_c = (a - a^T) + (T-1) - (a - a^T)/(1-a)
        const float a   = a2[o];
        const float aT  = powf(a, (float)T_STEPS);
        const float amT = a - aT;
        const float Sc  = amT + (float)(T_STEPS - 1) - amT / (1.0f - a);

        out[(size_t)(b0 + b) * N_OUT + o] = (s + __ldg(b2 + o) * Sc) * (1.0f / (float)T_STEPS);
    }
}

extern "C" void kernel_launch(void* const* d_in, const int* in_sizes, int n_in,
                              void* d_out, int out_size) {
    const float* x      = (const float*)d_in[0];
    const float* W1     = (const float*)d_in[1];
    const float* b1     = (const float*)d_in[2];
    const float* tau_n  = (const float*)d_in[3];
    const float* tau_m1 = (const float*)d_in[4];
    const float* W2     = (const float*)d_in[5];
    const float* b2     = (const float*)d_in[6];
    const float* tau_m2 = (const float*)d_in[7];
    const float* mask   = (const float*)d_in[8];
    float*       out    = (float*)d_out;

    cudaFuncSetAttribute(snn_dense_kernel,
                         cudaFuncAttributeMaxDynamicSharedMemorySize, SMEM_BYTES);

    snn_dense_kernel<<<NCTA, NTHR, SMEM_BYTES>>>(
        x, W1, b1, tau_n, tau_m1, W2, b2, tau_m2, mask, out);
}

// round 9
// speedup vs baseline: 4.4656x; 4.4656x over previous
#include <cuda_runtime.h>
#include <math.h>

#define B_TOT   512
#define T_STEPS 2000
#define N_INP   32
#define N_HID   200
#define N_OUT   3
#define KDIM    (N_INP + N_HID)
#define NB      4
#define NCTA    (B_TOT / NB)
#define NTHR    256
#define VTH     1.0f

// dynamic SMEM layout (bytes)
#define OFF_WRT   0
#define WRT_BYTES (N_HID * N_HID * 4)        // 160000: WrT[j][n] transposed recurrent weights
#define OFF_XS    (OFF_WRT + WRT_BYTES)
#define XS_BYTES  (4 * N_INP * NB * 4)       // 2048: 4-slot ring x[t&3][i] as float4 over batches
#define OFF_SUM   (OFF_XS + XS_BYTES)
#define SUM_BYTES (3 * 4 * 4)                // rotating summary[3 phases][4 batches]
#define OFF_MSK   (OFF_SUM + SUM_BYTES)
#define MSK_BYTES (3 * 7 * 4 * 4)            // rotating masks[3][7 warps][4 batches]
#define SMEM_BYTES (OFF_MSK + MSK_BYTES + 16)

__device__ __forceinline__ float sigm(float v) { return 1.0f / (1.0f + expf(-v)); }

__device__ __forceinline__ unsigned long long pack_dup(float w) {
    unsigned long long r;
    asm("mov.b64 %0, {%1, %1};" : "=l"(r) : "f"(w));
    return r;
}
__device__ __forceinline__ void fma_x2(unsigned long long& acc,
                                       unsigned long long a, unsigned long long b) {
    asm("fma.rn.f32x2 %0, %1, %2, %3;" : "=l"(acc) : "l"(a), "l"(b), "l"(acc));
}
__device__ __forceinline__ void unpack2(unsigned long long v, float& lo, float& hi) {
    asm("mov.b64 {%0, %1}, %2;" : "=f"(lo), "=f"(hi) : "l"(v));
}

extern __shared__ char smch[];

#define XG(bl, T) __ldg(xbase + (size_t)(bl) * (T_STEPS * N_INP) + (size_t)(T) * N_INP)

__global__ void __launch_bounds__(NTHR, 1)
snn_sparse_kernel(const float* __restrict__ x,
                  const float* __restrict__ W1,
                  const float* __restrict__ b1,
                  const float* __restrict__ tau_n,
                  const float* __restrict__ tau_m1,
                  const float* __restrict__ W2,
                  const float* __restrict__ b2,
                  const float* __restrict__ tau_m2,
                  const float* __restrict__ mask,
                  float* __restrict__ out)
{
    float*    WrT  = (float*)(smch + OFF_WRT);      // [200][200]
    float4*   xs4  = (float4*)(smch + OFF_XS);      // [4][32]
    unsigned* summ = (unsigned*)(smch + OFF_SUM);   // [3][4]
    unsigned* msk  = (unsigned*)(smch + OFF_MSK);   // [3][7][4]

    const int tid  = threadIdx.x;
    const int wid  = tid >> 5;
    const int lane = tid & 31;
    const int b0   = blockIdx.x * NB;

    // stage transposed recurrent weights (cols 32..231 of W1*mask)
    for (int idx = tid; idx < N_HID * N_HID; idx += NTHR) {
        int nn = idx / N_HID;
        int j  = idx - nn * N_HID;
        WrT[j * N_HID + nn] = W1[nn * KDIM + N_INP + j] * mask[nn * KDIM + N_INP + j];
    }
    if (tid < 12) summ[tid] = 0;

    const int  n       = tid;
    const bool active  = (n < N_HID);
    const bool is_comp = (wid < 7);

    float beta = 0.f, omb = 0.f, a1 = 0.f, oma1 = 0.f;
    unsigned long long wpk[N_INP];
    unsigned long long b1pk = 0ull;
    if (active) {
        beta = sigm(tau_n[n]);   omb  = 1.0f - beta;
        a1   = sigm(tau_m1[n]);  oma1 = 1.0f - a1;
        b1pk = pack_dup(b1[n]);
#pragma unroll
        for (int i = 0; i < N_INP; ++i)
            wpk[i] = pack_dup(W1[n * KDIM + i] * mask[n * KDIM + i]);
    } else {
#pragma unroll
        for (int i = 0; i < N_INP; ++i) wpk[i] = 0ull;
    }
    float a2v[N_OUT];
#pragma unroll
    for (int o = 0; o < N_OUT; ++o) a2v[o] = sigm(tau_m2[o]);

    float mem1[NB] = {0.f,0.f,0.f,0.f};
    float din [NB] = {0.f,0.f,0.f,0.f};
    float spk [NB] = {0.f,0.f,0.f,0.f};
    float Us  [NB] = {0.f,0.f,0.f,0.f};
    float spk0[NB] = {0.f,0.f,0.f,0.f};
    float Wac[N_OUT][NB];
#pragma unroll
    for (int o = 0; o < N_OUT; ++o)
#pragma unroll
        for (int b = 0; b < NB; ++b) Wac[o][b] = 0.f;
    float hs = 0.f;

    // warp 7: x staging prologue (slots 0,1 in smem; t=2,3 in regs)
    const float* xbase = x + (size_t)b0 * (T_STEPS * N_INP) + lane;
    float4 rC = make_float4(0.f,0.f,0.f,0.f), rD = rC;
    if (wid == 7) {
        float4 A, Bv;
        A.x  = XG(0,0); A.y  = XG(1,0); A.z  = XG(2,0); A.w  = XG(3,0);
        Bv.x = XG(0,1); Bv.y = XG(1,1); Bv.z = XG(2,1); Bv.w = XG(3,1);
        rC.x = XG(0,2); rC.y = XG(1,2); rC.z = XG(2,2); rC.w = XG(3,2);
        rD.x = XG(0,3); rD.y = XG(1,3); rD.z = XG(2,3); rD.w = XG(3,3);
        xs4[0 * N_INP + lane] = A;
        xs4[1 * N_INP + lane] = Bv;
    }
    __syncthreads();

    int pw = 0;  // write phase = t%3
#pragma unroll 1
    for (int t = 0; t < T_STEPS; ++t) {
        int pz = pw + 1; if (pz == 3) pz = 0;  // zero phase = (t+1)%3
        int pr = pz + 1; if (pr == 3) pr = 0;  // read phase = (t-1)%3

        if (is_comp) {
            // dense input projection: weights in regs, x broadcast from ring
            unsigned long long acc01 = b1pk, acc23 = b1pk;
            const ulonglong2* xv = (const ulonglong2*)(xs4 + (t & 3) * N_INP);
#pragma unroll
            for (int i = 0; i < N_INP; ++i) {
                ulonglong2 kv = xv[i];
                fma_x2(acc01, wpk[i], kv.x);
                fma_x2(acc23, wpk[i], kv.y);
            }
            float cur[NB];
            unpack2(acc01, cur[0], cur[1]);
            unpack2(acc23, cur[2], cur[3]);

            // event-driven recurrent input (steady state: 1 broadcast load + test)
            uint4 sv = *(const uint4*)(summ + pr * 4);
            if (sv.x | sv.y | sv.z | sv.w) {
#pragma unroll
                for (int b = 0; b < NB; ++b) {
                    unsigned sb = (b == 0) ? sv.x : (b == 1) ? sv.y : (b == 2) ? sv.z : sv.w;
                    if (sb) {
#pragma unroll 1
                        for (int w = 0; w < 7; ++w) {
                            unsigned m = msk[(pr * 7 + w) * 4 + b];
                            while (m) {
                                int j = (w << 5) + __ffs(m) - 1;
                                m &= m - 1;
                                if (active) cur[b] += WrT[j * N_HID + n];
                            }
                        }
                    }
                }
            }

            // neuron state update
            float sstep = 0.f;
#pragma unroll
            for (int b = 0; b < NB; ++b) {
                din[b]  = fmaf(beta, din[b], omb * cur[b]);
                mem1[b] = fmaf(a1, mem1[b], oma1 * din[b]) - spk[b];
                spk[b]  = (mem1[b] > VTH) ? 1.0f : 0.0f;
                sstep  += spk[b];
            }

            // publish spikes as bitmasks + summary
            unsigned bal0 = __ballot_sync(0xffffffffu, spk[0] > 0.f);
            unsigned bal1 = __ballot_sync(0xffffffffu, spk[1] > 0.f);
            unsigned bal2 = __ballot_sync(0xffffffffu, spk[2] > 0.f);
            unsigned bal3 = __ballot_sync(0xffffffffu, spk[3] > 0.f);
            if (lane < 4) {
                unsigned mw = (lane == 0) ? bal0 : (lane == 1) ? bal1
                            : (lane == 2) ? bal2 : bal3;
                msk[(pw * 7 + wid) * 4 + lane] = mw;
                if (mw) atomicOr(&summ[pw * 4 + lane], mw);
            }
            if (tid < 4) summ[pz * 4 + tid] = 0;

            // readout bookkeeping, gated behind sticky spike flag
            hs += sstep;
            if (hs > 0.f) {
                if (t == 0) {
#pragma unroll
                    for (int b = 0; b < NB; ++b) spk0[b] = spk[b];
                } else {
#pragma unroll
                    for (int b = 0; b < NB; ++b) Us[b] += spk[b];
                }
#pragma unroll
                for (int o = 0; o < N_OUT; ++o)
#pragma unroll
                    for (int b = 0; b < NB; ++b)
                        Wac[o][b] = fmaf(a2v[o], Wac[o][b], spk[b]);
            }
        } else {
            // warp 7: stage x(t+2), prefetch x(t+4)
            int tp2 = t + 2, tp4 = t + 4;
            if ((t & 1) == 0) {
                if (tp2 < T_STEPS) xs4[(tp2 & 3) * N_INP + lane] = rC;
                if (tp4 < T_STEPS) {
                    rC.x = XG(0,tp4); rC.y = XG(1,tp4);
                    rC.z = XG(2,tp4); rC.w = XG(3,tp4);
                }
            } else {
                if (tp2 < T_STEPS) xs4[(tp2 & 3) * N_INP + lane] = rD;
                if (tp4 < T_STEPS) {
                    rD.x = XG(0,tp4); rD.y = XG(1,tp4);
                    rD.z = XG(2,tp4); rD.w = XG(3,tp4);
                }
            }
        }
        __syncthreads();
        pw = pz;
    }

    // epilogue: out[b][o] = (sum_n W2[o,n]*A_o[n,b] + b2[o]*S_c[o]) / T
    float* red = (float*)smch;  // reuse WrT region: [12][N_HID]
    if (active) {
#pragma unroll
        for (int o = 0; o < N_OUT; ++o)
#pragma unroll
            for (int b = 0; b < NB; ++b)
                red[(o * NB + b) * N_HID + n] = Us[b] + a2v[o] * (spk0[b] - Wac[o][b]);
    }
    __syncthreads();

    if (tid < N_OUT * NB) {
        const int o = tid / NB;
        const int b = tid % NB;
        const float* Arow = red + tid * N_HID;
        const float* w2r  = W2 + o * N_HID;
        float s = 0.f;
#pragma unroll 8
        for (int j = 0; j < N_HID; ++j) s = fmaf(__ldg(w2r + j), Arow[j], s);

        const float a   = a2v[o];
        const float aT  = powf(a, (float)T_STEPS);
        const float amT = a - aT;
        const float Sc  = amT + (float)(T_STEPS - 1) - amT / (1.0f - a);

        out[(size_t)(b0 + b) * N_OUT + o] = (s + __ldg(b2 + o) * Sc) * (1.0f / (float)T_STEPS);
    }
}

extern "C" void kernel_launch(void* const* d_in, const int* in_sizes, int n_in,
                              void* d_out, int out_size) {
    const float* x      = (const float*)d_in[0];
    const float* W1     = (const float*)d_in[1];
    const float* b1     = (const float*)d_in[2];
    const float* tau_n  = (const float*)d_in[3];
    const float* tau_m1 = (const float*)d_in[4];
    const float* W2     = (const float*)d_in[5];
    const float* b2     = (const float*)d_in[6];
    const float* tau_m2 = (const float*)d_in[7];
    const float* mask   = (const float*)d_in[8];
    float*       out    = (float*)d_out;

    cudaFuncSetAttribute(snn_sparse_kernel,
                         cudaFuncAttributeMaxDynamicSharedMemorySize, SMEM_BYTES);

    snn_sparse_kernel<<<NCTA, NTHR, SMEM_BYTES>>>(
        x, W1, b1, tau_n, tau_m1, W2, b2, tau_m2, mask, out);
}

// round 10
// speedup vs baseline: 4.4753x; 1.0022x over previous
#include <cuda_runtime.h>
#include <math.h>

#define B_TOT   512
#define T_STEPS 2000
#define N_INP   32
#define N_HID   200
#define N_OUT   3
#define KDIM    (N_INP + N_HID)
#define NB      4
#define NCTA    (B_TOT / NB)
#define NTHR    256
#define VTH     1.0f

// dynamic SMEM layout (bytes)
#define OFF_WRT   0
#define WRT_BYTES (N_HID * N_HID * 4)        // 160000: WrT[j][n] transposed recurrent weights
#define OFF_XS    (OFF_WRT + WRT_BYTES)
#define XS_BYTES  (4 * N_INP * NB * 4)       // 2048: 4-slot ring x[t&3][i] as float4 over batches
#define OFF_SUM   (OFF_XS + XS_BYTES)
#define SUM_BYTES (3 * 4 * 4)                // rotating summary[3 phases][4 batches]
#define OFF_MSK   (OFF_SUM + SUM_BYTES)
#define MSK_BYTES (3 * 7 * 4 * 4)            // rotating masks[3][7 warps][4 batches]
#define SMEM_BYTES (OFF_MSK + MSK_BYTES + 16)

__device__ __forceinline__ float sigm(float v) { return 1.0f / (1.0f + expf(-v)); }

__device__ __forceinline__ unsigned long long pack_dup(float w) {
    unsigned long long r;
    asm("mov.b64 %0, {%1, %1};" : "=l"(r) : "f"(w));
    return r;
}
__device__ __forceinline__ void fma_x2(unsigned long long& acc,
                                       unsigned long long a, unsigned long long b) {
    asm("fma.rn.f32x2 %0, %1, %2, %3;" : "=l"(acc) : "l"(a), "l"(b), "l"(acc));
}
__device__ __forceinline__ void unpack2(unsigned long long v, float& lo, float& hi) {
    asm("mov.b64 {%0, %1}, %2;" : "=f"(lo), "=f"(hi) : "l"(v));
}

extern __shared__ char smch[];

#define XG(bl, T) __ldg(xbase + (size_t)(bl) * (T_STEPS * N_INP) + (size_t)(T) * N_INP)

__global__ void __launch_bounds__(NTHR, 1)
snn_sparse_kernel(const float* __restrict__ x,
                  const float* __restrict__ W1,
                  const float* __restrict__ b1,
                  const float* __restrict__ tau_n,
                  const float* __restrict__ tau_m1,
                  const float* __restrict__ W2,
                  const float* __restrict__ b2,
                  const float* __restrict__ tau_m2,
                  const float* __restrict__ mask,
                  float* __restrict__ out)
{
    float*    WrT  = (float*)(smch + OFF_WRT);      // [200][200]
    float4*   xs4  = (float4*)(smch + OFF_XS);      // [4][32]
    unsigned* summ = (unsigned*)(smch + OFF_SUM);   // [3][4]
    unsigned* msk  = (unsigned*)(smch + OFF_MSK);   // [3][7][4]

    const int tid  = threadIdx.x;
    const int wid  = tid >> 5;
    const int lane = tid & 31;
    const int b0   = blockIdx.x * NB;

    // stage transposed recurrent weights (cols 32..231 of W1*mask)
    for (int idx = tid; idx < N_HID * N_HID; idx += NTHR) {
        int nn = idx / N_HID;
        int j  = idx - nn * N_HID;
        WrT[j * N_HID + nn] = W1[nn * KDIM + N_INP + j] * mask[nn * KDIM + N_INP + j];
    }
    if (tid < 12) summ[tid] = 0;

    const int  n       = tid;
    const bool active  = (n < N_HID);
    const bool is_comp = (wid < 7);

    float beta = 0.f, omb = 0.f, a1 = 0.f, oma1 = 0.f;
    unsigned long long wpk[N_INP];
    unsigned long long b1pk = 0ull;
    if (active) {
        beta = sigm(tau_n[n]);   omb  = 1.0f - beta;
        a1   = sigm(tau_m1[n]);  oma1 = 1.0f - a1;
        b1pk = pack_dup(b1[n]);
#pragma unroll
        for (int i = 0; i < N_INP; ++i)
            wpk[i] = pack_dup(W1[n * KDIM + i] * mask[n * KDIM + i]);
    } else {
#pragma unroll
        for (int i = 0; i < N_INP; ++i) wpk[i] = 0ull;
    }
    float a2v[N_OUT];
#pragma unroll
    for (int o = 0; o < N_OUT; ++o) a2v[o] = sigm(tau_m2[o]);

    float mem1[NB] = {0.f,0.f,0.f,0.f};
    float din [NB] = {0.f,0.f,0.f,0.f};
    float spk [NB] = {0.f,0.f,0.f,0.f};
    float Us  [NB] = {0.f,0.f,0.f,0.f};
    float spk0[NB] = {0.f,0.f,0.f,0.f};
    float Wac[N_OUT][NB];
#pragma unroll
    for (int o = 0; o < N_OUT; ++o)
#pragma unroll
        for (int b = 0; b < NB; ++b) Wac[o][b] = 0.f;
    float hs = 0.f;

    // warp 7: x staging prologue (slots 0,1 in smem; t=2,3 in regs)
    const float* xbase = x + (size_t)b0 * (T_STEPS * N_INP) + lane;
    float4 rC = make_float4(0.f,0.f,0.f,0.f), rD = rC;
    if (wid == 7) {
        float4 A, Bv;
        A.x  = XG(0,0); A.y  = XG(1,0); A.z  = XG(2,0); A.w  = XG(3,0);
        Bv.x = XG(0,1); Bv.y = XG(1,1); Bv.z = XG(2,1); Bv.w = XG(3,1);
        rC.x = XG(0,2); rC.y = XG(1,2); rC.z = XG(2,2); rC.w = XG(3,2);
        rD.x = XG(0,3); rD.y = XG(1,3); rD.z = XG(2,3); rD.w = XG(3,3);
        xs4[0 * N_INP + lane] = A;
        xs4[1 * N_INP + lane] = Bv;
    }
    __syncthreads();

    int pw = 0;  // write phase = t%3
#pragma unroll 1
    for (int t = 0; t < T_STEPS; ++t) {
        int pz = pw + 1; if (pz == 3) pz = 0;  // zero phase = (t+1)%3
        int pr = pz + 1; if (pr == 3) pr = 0;  // read phase = (t-1)%3

        if (is_comp) {
            // dense input projection: weights in regs, x broadcast from ring
            unsigned long long acc01 = b1pk, acc23 = b1pk;
            const ulonglong2* xv = (const ulonglong2*)(xs4 + (t & 3) * N_INP);
#pragma unroll
            for (int i = 0; i < N_INP; ++i) {
                ulonglong2 kv = xv[i];
                fma_x2(acc01, wpk[i], kv.x);
                fma_x2(acc23, wpk[i], kv.y);
            }
            float cur[NB];
            unpack2(acc01, cur[0], cur[1]);
            unpack2(acc23, cur[2], cur[3]);

            // event-driven recurrent input (steady state: 1 broadcast load + test)
            uint4 sv = *(const uint4*)(summ + pr * 4);
            if (sv.x | sv.y | sv.z | sv.w) {
#pragma unroll
                for (int b = 0; b < NB; ++b) {
                    unsigned sb = (b == 0) ? sv.x : (b == 1) ? sv.y : (b == 2) ? sv.z : sv.w;
                    if (sb) {
#pragma unroll 1
                        for (int w = 0; w < 7; ++w) {
                            unsigned m = msk[(pr * 7 + w) * 4 + b];
                            while (m) {
                                int j = (w << 5) + __ffs(m) - 1;
                                m &= m - 1;
                                if (active) cur[b] += WrT[j * N_HID + n];
                            }
                        }
                    }
                }
            }

            // neuron state update
            float sstep = 0.f;
#pragma unroll
            for (int b = 0; b < NB; ++b) {
                din[b]  = fmaf(beta, din[b], omb * cur[b]);
                mem1[b] = fmaf(a1, mem1[b], oma1 * din[b]) - spk[b];
                spk[b]  = (mem1[b] > VTH) ? 1.0f : 0.0f;
                sstep  += spk[b];
            }

            // publish spikes as bitmasks + summary
            unsigned bal0 = __ballot_sync(0xffffffffu, spk[0] > 0.f);
            unsigned bal1 = __ballot_sync(0xffffffffu, spk[1] > 0.f);
            unsigned bal2 = __ballot_sync(0xffffffffu, spk[2] > 0.f);
            unsigned bal3 = __ballot_sync(0xffffffffu, spk[3] > 0.f);
            if (lane < 4) {
                unsigned mw = (lane == 0) ? bal0 : (lane == 1) ? bal1
                            : (lane == 2) ? bal2 : bal3;
                msk[(pw * 7 + wid) * 4 + lane] = mw;
                if (mw) atomicOr(&summ[pw * 4 + lane], mw);
            }
            if (tid < 4) summ[pz * 4 + tid] = 0;

            // readout bookkeeping, gated behind sticky spike flag
            hs += sstep;
            if (hs > 0.f) {
                if (t == 0) {
#pragma unroll
                    for (int b = 0; b < NB; ++b) spk0[b] = spk[b];
                } else {
#pragma unroll
                    for (int b = 0; b < NB; ++b) Us[b] += spk[b];
                }
#pragma unroll
                for (int o = 0; o < N_OUT; ++o)
#pragma unroll
                    for (int b = 0; b < NB; ++b)
                        Wac[o][b] = fmaf(a2v[o], Wac[o][b], spk[b]);
            }
        } else {
            // warp 7: stage x(t+2), prefetch x(t+4)
            int tp2 = t + 2, tp4 = t + 4;
            if ((t & 1) == 0) {
                if (tp2 < T_STEPS) xs4[(tp2 & 3) * N_INP + lane] = rC;
                if (tp4 < T_STEPS) {
                    rC.x = XG(0,tp4); rC.y = XG(1,tp4);
                    rC.z = XG(2,tp4); rC.w = XG(3,tp4);
                }
            } else {
                if (tp2 < T_STEPS) xs4[(tp2 & 3) * N_INP + lane] = rD;
                if (tp4 < T_STEPS) {
                    rD.x = XG(0,tp4); rD.y = XG(1,tp4);
                    rD.z = XG(2,tp4); rD.w = XG(3,tp4);
                }
            }
        }
        __syncthreads();
        pw = pz;
    }

    // epilogue: out[b][o] = (sum_n W2[o,n]*A_o[n,b] + b2[o]*S_c[o]) / T
    float* red = (float*)smch;  // reuse WrT region: [12][N_HID]
    if (active) {
#pragma unroll
        for (int o = 0; o < N_OUT; ++o)
#pragma unroll
            for (int b = 0; b < NB; ++b)
                red[(o * NB + b) * N_HID + n] = Us[b] + a2v[o] * (spk0[b] - Wac[o][b]);
    }
    __syncthreads();

    if (tid < N_OUT * NB) {
        const int o = tid / NB;
        const int b = tid % NB;
        const float* Arow = red + tid * N_HID;
        const float* w2r  = W2 + o * N_HID;
        float s = 0.f;
#pragma unroll 8
        for (int j = 0; j < N_HID; ++j) s = fmaf(__ldg(w2r + j), Arow[j], s);

        const float a   = a2v[o];
        const float aT  = powf(a, (float)T_STEPS);
        const float amT = a - aT;
        const float Sc  = amT + (float)(T_STEPS - 1) - amT / (1.0f - a);

        out[(size_t)(b0 + b) * N_OUT + o] = (s + __ldg(b2 + o) * Sc) * (1.0f / (float)T_STEPS);
    }
}

extern "C" void kernel_launch(void* const* d_in, const int* in_sizes, int n_in,
                              void* d_out, int out_size) {
    const float* x      = (const float*)d_in[0];
    const float* W1     = (const float*)d_in[1];
    const float* b1     = (const float*)d_in[2];
    const float* tau_n  = (const float*)d_in[3];
    const float* tau_m1 = (const float*)d_in[4];
    const float* W2     = (const float*)d_in[5];
    const float* b2     = (const float*)d_in[6];
    const float* tau_m2 = (const float*)d_in[7];
    const float* mask   = (const float*)d_in[8];
    float*       out    = (float*)d_out;

    cudaFuncSetAttribute(snn_sparse_kernel,
                         cudaFuncAttributeMaxDynamicSharedMemorySize, SMEM_BYTES);

    snn_sparse_kernel<<<NCTA, NTHR, SMEM_BYTES>>>(
        x, W1, b1, tau_n, tau_m1, W2, b2, tau_m2, mask, out);
}